// round 17
// baseline (speedup 1.0000x reference)
#include <cuda_runtime.h>
#include <cuda_fp16.h>
#include <math.h>
#include <stdint.h>

#define B_TOK   4096
#define DM      1024
#define DH      2048
#define N_TILES 8

typedef __half fp16;

// ---------------- scratch (device globals; no allocation allowed) -----------
__device__ fp16  g_xhi [B_TOK * DM];
__device__ fp16  g_xlo [B_TOK * DM];
__device__ float g_Hr  [B_TOK * DM];
__device__ fp16  g_H2  [B_TOK * DH];
__device__ fp16  g_sel [B_TOK * DM];
// pre-converted fp16 weights (same [K][N] layout as the fp32 inputs)
__device__ fp16  g_Wr1h[DM * DM], g_Wr1l[DM * DM];
__device__ fp16  g_W1h [N_TILES * DM * DH];
__device__ fp16  g_W2h [N_TILES * DH * DM];
__device__ fp16  g_Woh [DM * DM];
__device__ int   g_tile[B_TOK];
__device__ int   g_perm[B_TOK];
__device__ int   g_cnt[N_TILES];
__device__ int   g_off[N_TILES];
__device__ int   g_cur[N_TILES];

// ---------------- helpers ----------------------------------------------------
__device__ __forceinline__ uint32_t smem_u32(const void* p) {
    uint32_t a;
    asm("{ .reg .u64 t; cvta.to.shared.u64 t, %1; cvt.u32.u64 %0, t; }"
        : "=r"(a) : "l"(p));
    return a;
}
__device__ __forceinline__ void cp_async16(uint32_t dst, const void* src) {
    asm volatile("cp.async.cg.shared.global [%0], [%1], 16;"
                 :: "r"(dst), "l"(src) : "memory");
}
__device__ __forceinline__ void cp_commit() {
    asm volatile("cp.async.commit_group;" ::: "memory");
}
__device__ __forceinline__ void cp_wait1() {
    asm volatile("cp.async.wait_group 1;" ::: "memory");
}
__device__ __forceinline__ void ldsm_x4(uint32_t* r, uint32_t addr) {
    asm volatile("ldmatrix.sync.aligned.m8n8.x4.shared.b16 {%0,%1,%2,%3}, [%4];"
                 : "=r"(r[0]), "=r"(r[1]), "=r"(r[2]), "=r"(r[3]) : "r"(addr));
}
__device__ __forceinline__ void ldsm_x4_t(uint32_t* r, uint32_t addr) {
    asm volatile("ldmatrix.sync.aligned.m8n8.x4.trans.shared.b16 {%0,%1,%2,%3}, [%4];"
                 : "=r"(r[0]), "=r"(r[1]), "=r"(r[2]), "=r"(r[3]) : "r"(addr));
}
__device__ __forceinline__ void mma16816(float* c, const uint32_t* a, const uint32_t* b) {
    asm volatile("mma.sync.aligned.m16n8k16.row.col.f32.f16.f16.f32 "
                 "{%0,%1,%2,%3}, {%4,%5,%6,%7}, {%8,%9}, {%0,%1,%2,%3};"
                 : "+f"(c[0]), "+f"(c[1]), "+f"(c[2]), "+f"(c[3])
                 : "r"(a[0]), "r"(a[1]), "r"(a[2]), "r"(a[3]),
                   "r"(b[0]), "r"(b[1]));
}
__device__ __forceinline__ float gelu_exact(float v) {
    return 0.5f * v * (1.0f + erff(v * 0.70710678118654752440f));
}
__device__ __forceinline__ uint32_t pack_hi2(float a, float b) {
    __half2 p(__float2half_rn(a), __float2half_rn(b));
    return *(uint32_t*)&p;
}
__device__ __forceinline__ uint32_t pack_lo2(float a, float b, uint32_t hi) {
    __half2 h = *(__half2*)&hi;
    __half2 p(__float2half_rn(a - __half2float(h.x)),
              __float2half_rn(b - __half2float(h.y)));
    return *(uint32_t*)&p;
}

// ---------------- fused prep: split x + convert all weights ------------------
// Region sizes in float4-PAIRS (8 floats / 16 fp16 per thread):
//   x 524288 | Wr1 131072 | W1 2097152 | W2 2097152 | Wo 131072
// total 4,980,736 pairs -> 19,456 blocks x 256.
#define PR_X   524288
#define PR_WR1 (PR_X + 131072)
#define PR_W1  (PR_WR1 + 2097152)
#define PR_W2  (PR_W1 + 2097152)
#define PR_END (PR_W2 + 131072)

__device__ __forceinline__ void cvt_pair(const float4* s, uint4* dh) {
    float4 a = s[0], b = s[1];
    *dh = make_uint4(pack_hi2(a.x, a.y), pack_hi2(a.z, a.w),
                     pack_hi2(b.x, b.y), pack_hi2(b.z, b.w));
}
__device__ __forceinline__ void split_pair(const float4* s, uint4* dh, uint4* dl) {
    float4 a = s[0], b = s[1];
    uint32_t h0 = pack_hi2(a.x, a.y), h1 = pack_hi2(a.z, a.w);
    uint32_t h2 = pack_hi2(b.x, b.y), h3 = pack_hi2(b.z, b.w);
    *dh = make_uint4(h0, h1, h2, h3);
    *dl = make_uint4(pack_lo2(a.x, a.y, h0), pack_lo2(a.z, a.w, h1),
                     pack_lo2(b.x, b.y, h2), pack_lo2(b.z, b.w, h3));
}

__global__ void prep_kernel(const float* __restrict__ x,
                            const float* __restrict__ Wr1,
                            const float* __restrict__ W1,
                            const float* __restrict__ W2,
                            const float* __restrict__ Wo,
                            fp16* __restrict__ xhi,  fp16* __restrict__ xlo,
                            fp16* __restrict__ Wr1h, fp16* __restrict__ Wr1l,
                            fp16* __restrict__ W1h,  fp16* __restrict__ W2h,
                            fp16* __restrict__ Woh)
{
    if (blockIdx.x == 0 && threadIdx.x < N_TILES) {
        g_cnt[threadIdx.x] = 0;
        g_cur[threadIdx.x] = 0;
    }
    const int t = blockIdx.x * blockDim.x + threadIdx.x;   // pair index
    if (t < PR_X) {
        const int i = t;
        split_pair((const float4*)x + 2 * (size_t)i,
                   (uint4*)xhi + i, (uint4*)xlo + i);
    } else if (t < PR_WR1) {
        const int i = t - PR_X;
        split_pair((const float4*)Wr1 + 2 * (size_t)i,
                   (uint4*)Wr1h + i, (uint4*)Wr1l + i);
    } else if (t < PR_W1) {
        const int i = t - PR_WR1;
        cvt_pair((const float4*)W1 + 2 * (size_t)i, (uint4*)W1h + i);
    } else if (t < PR_W2) {
        const int i = t - PR_W1;
        cvt_pair((const float4*)W2 + 2 * (size_t)i, (uint4*)W2h + i);
    } else {
        const int i = t - PR_W2;
        cvt_pair((const float4*)Wo + 2 * (size_t)i, (uint4*)Woh + i);
    }
}

// ---------------- router logits + argmax (float4 loads) ----------------------
__global__ __launch_bounds__(256) void router_argmax_kernel(
    const float* __restrict__ Hr, const float* __restrict__ Wr2,
    const float* __restrict__ br2,
    float* __restrict__ out_logits, float* __restrict__ out_idx)
{
    const int token = blockIdx.x * 8 + (threadIdx.x >> 5);
    const int lane  = threadIdx.x & 31;
    const float4* h4 = (const float4*)(Hr + (size_t)token * DM);

    float acc[N_TILES];
#pragma unroll
    for (int n = 0; n < N_TILES; n++) acc[n] = 0.f;

    for (int k4 = lane; k4 < DM / 4; k4 += 32) {
        float4 hv = h4[k4];
        const float4* w = (const float4*)(Wr2 + (size_t)k4 * 4 * N_TILES);
#pragma unroll
        for (int j = 0; j < 4; j++) {
            float hj = (j == 0) ? hv.x : (j == 1) ? hv.y : (j == 2) ? hv.z : hv.w;
            float4 w0 = w[j * 2 + 0];
            float4 w1 = w[j * 2 + 1];
            acc[0] = fmaf(hj, w0.x, acc[0]); acc[1] = fmaf(hj, w0.y, acc[1]);
            acc[2] = fmaf(hj, w0.z, acc[2]); acc[3] = fmaf(hj, w0.w, acc[3]);
            acc[4] = fmaf(hj, w1.x, acc[4]); acc[5] = fmaf(hj, w1.y, acc[5]);
            acc[6] = fmaf(hj, w1.z, acc[6]); acc[7] = fmaf(hj, w1.w, acc[7]);
        }
    }
#pragma unroll
    for (int n = 0; n < N_TILES; n++)
#pragma unroll
        for (int s = 16; s > 0; s >>= 1)
            acc[n] += __shfl_xor_sync(0xFFFFFFFFu, acc[n], s);
    if (lane == 0) {
        float best = -1e30f; int bi = 0;
#pragma unroll
        for (int n = 0; n < N_TILES; n++) {
            float l = (acc[n] + br2[n]) * 2.0f;
            if (out_logits) out_logits[(size_t)token * N_TILES + n] = l;
            if (l > best) { best = l; bi = n; }
        }
        g_tile[token] = bi;
        atomicAdd(&g_cnt[bi], 1);
        if (out_idx) out_idx[token] = (float)bi;
    }
}

// scatter also derives offsets from g_cnt (block 0 persists g_off).
__global__ void scatter_kernel() {
    int i = blockIdx.x * blockDim.x + threadIdx.x;
    int c0 = g_cnt[0], c1 = g_cnt[1], c2 = g_cnt[2], c3 = g_cnt[3];
    int c4 = g_cnt[4], c5 = g_cnt[5], c6 = g_cnt[6];
    int off[N_TILES];
    off[0] = 0;
    off[1] = c0;            off[2] = off[1] + c1;  off[3] = off[2] + c2;
    off[4] = off[3] + c3;   off[5] = off[4] + c4;  off[6] = off[5] + c5;
    off[7] = off[6] + c6;
    if (blockIdx.x == 0 && threadIdx.x < N_TILES)
        g_off[threadIdx.x] = off[threadIdx.x];
    if (i < B_TOK) {
        int t = g_tile[i];
        int pos = off[t] + atomicAdd(&g_cur[t], 1);
        g_perm[pos] = i;
    }
}

// ---------------- HMMA fp16 GEMM, pre-converted fp16 weights -----------------
// C[M,N] = act(A[M,K] @ W[K,N] + b). W given as fp16 [K][N] (hi, and lo for
// NTERM==3). Both A and B tiles arrive via cp.async (no in-loop conversion).
// NTERM==3 (router): BK=16, D = Ah*Bh + Ah*Bl + Al*Bh (err ~2^-22; 1 CTA/SM).
// NTERM==1 (big GEMMs): BK=32, D = Ah*Bh (A-lo ~2^-11 and W rounding ~2.8e-4
//   accepted). 2 CTAs/SM via launch bounds.
// Block 128x128, 256 threads, 8 warps (2Mx4N). 3 x 16KB = 48KB static smem.

#define SOFF_ALO 4096
#define SOFF_BHI 8192
#define SOFF_BLO 12288
#define STAGE_B  16384
#define NSTAGE   3

template<int MODE, int NTERM, bool ACT, bool F32OUT>
__global__ void __launch_bounds__(256, (NTERM == 1) ? 2 : 1) hgemm_kernel(
    const fp16* __restrict__ Ahi, const fp16* __restrict__ Alo,
    const fp16* __restrict__ Wh, const fp16* __restrict__ Wl,
    const float* __restrict__ bg,
    float* __restrict__ Cf, fp16* __restrict__ Ch,
    int N, int K, int M0)
{
    constexpr int BKT = (NTERM == 1) ? 32 : 16;   // k per stage

    const int tile = (MODE == 0) ? 0 : blockIdx.z;
    int Mvalid, moff;
    if (MODE == 0) { Mvalid = M0;          moff = 0; }
    else           { Mvalid = g_cnt[tile]; moff = g_off[tile]; }

    const int mstart = blockIdx.y * 128;
    if (mstart >= Mvalid) return;
    const int nstart = blockIdx.x * 128;

    __shared__ __align__(128) char smem[NSTAGE * STAGE_B];
    const uint32_t sb = smem_u32(smem);
    const int tid  = threadIdx.x;
    const int wid  = tid >> 5;
    const int lane = tid & 31;
    const int warp_m = (wid & 1) * 64;
    const int warp_n = (wid >> 1) * 32;
    const int g     = lane >> 2;
    const int tig   = lane & 3;
    const int matid = lane >> 3;
    const int mrow8 = lane & 7;

    // ---- A loader (cp.async) ----
    const int lrow = tid >> 1;
    int mg = mstart + lrow; if (mg > Mvalid - 1) mg = Mvalid - 1;
    size_t aidx;
    if (MODE == 0)      aidx = (size_t)mg;
    else if (MODE == 1) aidx = (size_t)g_perm[moff + mg];
    else                aidx = (size_t)(moff + mg);
    const fp16* gah = Ahi + aidx * (size_t)K;
    const fp16* gal = (NTERM == 3) ? (Alo + aidx * (size_t)K) : nullptr;
    const int kc   = tid & 1;            // NTERM3 chunk
    const int keo  = kc * 8;
    const uint32_t astoff3 = (uint32_t)lrow * 32 + (uint32_t)kc * 16;
    const int kc0  = (tid & 1) * 2;      // NTERM1 first chunk
    const int aswz_st = (lrow >> 1) & 3;
    const uint32_t ast1_0 = (uint32_t)lrow * 64 + (uint32_t)((kc0      ^ aswz_st) * 16);
    const uint32_t ast1_1 = (uint32_t)lrow * 64 + (uint32_t)(((kc0 + 1) ^ aswz_st) * 16);
    const int ke1_0 = kc0 * 8, ke1_1 = ke1_0 + 8;

    // ---- B loader (cp.async from fp16 weights, swizzled dst) ----
    const fp16* gbh = Wh + (size_t)tile * (size_t)K * (size_t)N + nstart;
    const fp16* gbl = (NTERM == 3)
        ? (Wl + (size_t)tile * (size_t)K * (size_t)N + nstart) : nullptr;
    const int b1row = tid >> 3;
    const int b1c0  = tid & 7;
    const int b1c1  = b1c0 + 8;
    const uint32_t b1st0 = (uint32_t)b1row * 256
                         + (uint32_t)((((b1c0 >> 1) ^ (b1row & 7)) * 32) + (b1c0 & 1) * 16);
    const uint32_t b1st1 = (uint32_t)b1row * 256
                         + (uint32_t)((((b1c1 >> 1) ^ (b1row & 7)) * 32) + (b1c1 & 1) * 16);
    const int b3row = tid >> 4;
    const int b3c   = tid & 15;
    const uint32_t b3st = (uint32_t)b3row * 256
                        + (uint32_t)((((b3c >> 1) ^ (b3row & 7)) * 32) + (b3c & 1) * 16);

    // ---- ldmatrix addresses ----
    const uint32_t a_ls3 = (uint32_t)(warp_m + (matid & 1) * 8 + mrow8) * 32
                         + (uint32_t)(matid >> 1) * 16;
    const int arow_base = warp_m + (matid & 1) * 8 + mrow8;   // + mt*16
    const uint32_t a_base1 = (uint32_t)arow_base * 64;
    const int aswz_ld = (arow_base >> 1) & 3;
    const int matid2 = matid >> 1;
    const uint32_t bt_row = (uint32_t)((matid & 1) * 8 + mrow8) * 256
                          + (uint32_t)(matid >> 1) * 16;
    const uint32_t bt_c0 = (uint32_t)((((warp_n >> 4) + 0) ^ mrow8) * 32);
    const uint32_t bt_c1 = (uint32_t)((((warp_n >> 4) + 1) ^ mrow8) * 32);

    const int nk = K / BKT;

    auto cpStage = [&](int kt, uint32_t buf) {
        const int k0 = kt * BKT;
        if (NTERM == 1) {
            cp_async16(buf + ast1_0, gah + k0 + ke1_0);
            cp_async16(buf + ast1_1, gah + k0 + ke1_1);
            const fp16* br = gbh + (size_t)(k0 + b1row) * N;
            cp_async16(buf + SOFF_BHI + b1st0, br + b1c0 * 8);
            cp_async16(buf + SOFF_BHI + b1st1, br + b1c1 * 8);
        } else {
            cp_async16(buf + astoff3, gah + k0 + keo);
            cp_async16(buf + SOFF_ALO + astoff3, gal + k0 + keo);
            const fp16* brh = gbh + (size_t)(k0 + b3row) * N;
            const fp16* brl = gbl + (size_t)(k0 + b3row) * N;
            cp_async16(buf + SOFF_BHI + b3st, brh + b3c * 8);
            cp_async16(buf + SOFF_BLO + b3st, brl + b3c * 8);
        }
    };

    // ---- prologue ----
    cpStage(0, sb);             cp_commit();
    cpStage(1, sb + STAGE_B);   cp_commit();

    float acc[4][4][4];
#pragma unroll
    for (int i = 0; i < 4; i++)
#pragma unroll
        for (int j = 0; j < 4; j++)
#pragma unroll
            for (int c = 0; c < 4; c++) acc[i][j][c] = 0.f;

    int sc = 0;   // stage of kt
    int sp = 2;   // stage of kt+2
    for (int kt = 0; kt < nk; kt++) {
        cp_wait1();
        __syncthreads();

        if (kt + 2 < nk) cpStage(kt + 2, sb + sp * STAGE_B);
        cp_commit();

        const uint32_t st = sb + sc * STAGE_B;

        if (NTERM == 3) {
            uint32_t Bh[8], Bl[8];
            ldsm_x4_t(&Bh[0], st + SOFF_BHI + bt_row + bt_c0);
            ldsm_x4_t(&Bh[4], st + SOFF_BHI + bt_row + bt_c1);
            ldsm_x4_t(&Bl[0], st + SOFF_BLO + bt_row + bt_c0);
            ldsm_x4_t(&Bl[4], st + SOFF_BLO + bt_row + bt_c1);
#pragma unroll
            for (int mt = 0; mt < 4; mt++) {
                const uint32_t aa = st + a_ls3 + (uint32_t)mt * 16 * 32;
                uint32_t Ah[4], Al[4];
                ldsm_x4(Ah, aa);
                ldsm_x4(Al, aa + SOFF_ALO);
#pragma unroll
                for (int nt = 0; nt < 4; nt++) {
                    const uint32_t* bh = &Bh[(nt >> 1) * 4 + (nt & 1) * 2];
                    const uint32_t* bl = &Bl[(nt >> 1) * 4 + (nt & 1) * 2];
                    mma16816(acc[mt][nt], Ah, bh);
                    mma16816(acc[mt][nt], Ah, bl);
                    mma16816(acc[mt][nt], Al, bh);
                }
            }
        } else {
#pragma unroll
            for (int ks = 0; ks < 2; ks++) {
                uint32_t Bh[8];
                const uint32_t bb = st + SOFF_BHI + bt_row + (uint32_t)ks * 16 * 256;
                ldsm_x4_t(&Bh[0], bb + bt_c0);
                ldsm_x4_t(&Bh[4], bb + bt_c1);
                const int kchunk = ks * 2 + matid2;
                const uint32_t ak = (uint32_t)((kchunk ^ aswz_ld) * 16);
#pragma unroll
                for (int mt = 0; mt < 4; mt++) {
                    uint32_t Ah[4];
                    ldsm_x4(Ah, st + a_base1 + (uint32_t)mt * 1024 + ak);
#pragma unroll
                    for (int nt = 0; nt < 4; nt++)
                        mma16816(acc[mt][nt], Ah, &Bh[(nt >> 1) * 4 + (nt & 1) * 2]);
                }
            }
        }

        sc = (sc == NSTAGE - 1) ? 0 : sc + 1;
        sp = (sp == NSTAGE - 1) ? 0 : sp + 1;
    }

    // ---- epilogue ----
    const float* bias = bg + (size_t)tile * N;
#pragma unroll
    for (int mt = 0; mt < 4; mt++) {
#pragma unroll
        for (int half = 0; half < 2; half++) {
            const int m = mstart + warp_m + mt * 16 + g + half * 8;
            if (m >= Mvalid) continue;
            size_t orow;
            if (MODE == 0)      orow = (size_t)m;
            else if (MODE == 1) orow = (size_t)(moff + m);
            else                orow = (size_t)g_perm[moff + m];
#pragma unroll
            for (int nt = 0; nt < 4; nt++) {
                const int n = nstart + warp_n + nt * 8 + tig * 2;
                float v0 = acc[mt][nt][half * 2 + 0] + bias[n + 0];
                float v1 = acc[mt][nt][half * 2 + 1] + bias[n + 1];
                if (ACT) { v0 = gelu_exact(v0); v1 = gelu_exact(v1); }
                if (F32OUT) {
                    *(float2*)(Cf + orow * (size_t)N + n) = make_float2(v0, v1);
                } else {
                    *(uint32_t*)(Ch + orow * (size_t)N + n) = pack_hi2(v0, v1);
                }
            }
        }
    }
}

// ---------------- launch -----------------------------------------------------
// __device__ globals passed as kernel args MUST be resolved through
// cudaGetSymbolAddress (host shadow vs device copy under ATS on GB300).
#define SYMADDR(T, var, sym) \
    T* var; { void* _p; cudaGetSymbolAddress(&_p, sym); var = (T*)_p; }

extern "C" void kernel_launch(void* const* d_in, const int* in_sizes, int n_in,
                              void* d_out, int out_size)
{
    const float* x   = (const float*)d_in[0];
    const float* Wr1 = (const float*)d_in[1];
    const float* br1 = (const float*)d_in[2];
    const float* Wr2 = (const float*)d_in[3];
    const float* br2 = (const float*)d_in[4];
    const float* W1  = (const float*)d_in[5];
    const float* b1  = (const float*)d_in[6];
    const float* W2  = (const float*)d_in[7];
    const float* b2  = (const float*)d_in[8];
    const float* Wo  = (const float*)d_in[9];
    const float* bo  = (const float*)d_in[10];

    SYMADDR(fp16,  xhi,  g_xhi);   SYMADDR(fp16, xlo,  g_xlo);
    SYMADDR(float, Hr,   g_Hr);
    SYMADDR(fp16,  H2,   g_H2);    SYMADDR(fp16, sel,  g_sel);
    SYMADDR(fp16,  Wr1h, g_Wr1h);  SYMADDR(fp16, Wr1l, g_Wr1l);
    SYMADDR(fp16,  W1h,  g_W1h);
    SYMADDR(fp16,  W2h,  g_W2h);
    SYMADDR(fp16,  Woh,  g_Woh);

    float* out = (float*)d_out;
    float* out_main   = out;
    float* out_idx    = nullptr;
    float* out_logits = nullptr;
    const long long need_all = (long long)B_TOK * DM + B_TOK + (long long)B_TOK * N_TILES;
    if ((long long)out_size >= need_all) {
        out_idx    = out + (size_t)B_TOK * DM;
        out_logits = out + (size_t)B_TOK * DM + B_TOK;
    } else if ((long long)out_size >= (long long)B_TOK * DM + B_TOK) {
        out_idx = out + (size_t)B_TOK * DM;
    }

    // 1) fused prep: split x + convert all weights + zero counters [launch 1]
    prep_kernel<<<PR_END / 256, 256>>>(x, Wr1, W1, W2, Wo,
                                       xhi, xlo, Wr1h, Wr1l, W1h, W2h, Woh);

    // 2) router hidden (fp16 x3, BK=16 — near-exact)               [launch 2]
    hgemm_kernel<0, 3, true, true><<<dim3(DM / 128, B_TOK / 128), 256>>>(
        xhi, xlo, Wr1h, Wr1l, br1, Hr, nullptr, DM, DM, B_TOK);

    // 3) logits + argmax + counts                                  [launch 3]
    router_argmax_kernel<<<B_TOK / 8, 256>>>(Hr, Wr2, br2, out_logits, out_idx);

    // 4) offsets (in-kernel prefix) + scatter                       [launch 4]
    scatter_kernel<<<B_TOK / 256, 256>>>();

    // 5) tile MLP layer 1 (gather, gelu, 1-term BK=32)              [launch 5]
    hgemm_kernel<1, 1, true, false><<<dim3(DH / 128, B_TOK / 128, N_TILES), 256>>>(
        xhi, nullptr, W1h, nullptr, b1, nullptr, H2, DH, DM, 0);

    // 6) tile MLP layer 2 (compact->scatter, 1-term BK=32)          [launch 6]
    hgemm_kernel<2, 1, false, false><<<dim3(DM / 128, B_TOK / 128, N_TILES), 256>>>(
        H2, nullptr, W2h, nullptr, b2, nullptr, sel, DM, DH, 0);

    // 7) output projection (fp32 out), 1-term BK=32                 [launch 7]
    hgemm_kernel<0, 1, false, true><<<dim3(DM / 128, B_TOK / 128), 256>>>(
        sel, nullptr, Woh, nullptr, bo, out_main, nullptr, DM, DM, B_TOK);
}